// round 1
// baseline (speedup 1.0000x reference)
#include <cuda_runtime.h>

// ExtractPatch: B=8, H=W=1024, N=4096 matches, R=8 -> 17x17 patches.
// Output (B, N, 2*289) fp32: [normalize(p1), normalize(p2)] per match.
// p1[k] = image1[b, m1 + k%17 - 8, m0 + k/17 - 8]  (zero outside [0,1024))
// p2[k] = image2[b, m3 + k%17 - 8, m2 + k/17 - 8]
// normalize: (p - mean) / (std_ddof1 + 1e-4)

#define D      17
#define PATCH  289          // D*D
#define RADIUS 8
#define HW     1024
#define NMATCH 4096
#define BATCH  8
#define WARPS_PER_BLOCK 8

__global__ __launch_bounds__(256, 4)
void extract_patch_kernel(const float* __restrict__ img1,
                          const float* __restrict__ img2,
                          const int*   __restrict__ matches,
                          float*       __restrict__ out)
{
    // +19 pad (odd stride) -> conflict-free transposed reads
    __shared__ float smem[WARPS_PER_BLOCK][D][19];

    const int warpId = threadIdx.x >> 5;
    const int lane   = threadIdx.x & 31;

    // global patch id: 2 patches (img1/img2) per (b, n)
    const int gp    = blockIdx.x * WARPS_PER_BLOCK + warpId;   // 0 .. 65535
    const int which = gp & 1;                                  // 0 -> p1, 1 -> p2
    const int bn    = gp >> 1;                                 // b*NMATCH + n
    const int b     = bn >> 12;                                // NMATCH = 4096

    const float* __restrict__ img = which ? img2 : img1;
    const float* __restrict__ ib  = img + (size_t)b * (HW * HW);

    const int* m  = matches + bn * 4 + which * 2;
    const int  mx = m[0];   // column base
    const int  my = m[1];   // row base

    // ---- load patch in IMAGE-ROW order (coalesced), accumulate sum/sumsq ----
    float sum = 0.f, sumsq = 0.f;
    #pragma unroll
    for (int t = 0; t < 10; ++t) {
        const int idx = t * 32 + lane;         // 0 .. 319
        if (idx < PATCH) {
            const int r = idx / D;             // image row offset 0..16
            const int c = idx % D;             // image col offset 0..16
            const int y = my + r - RADIUS;
            const int x = mx + c - RADIUS;
            float v = 0.f;
            if ((unsigned)y < HW && (unsigned)x < HW)
                v = __ldg(ib + y * HW + x);
            smem[warpId][r][c] = v;
            sum   += v;
            sumsq  = fmaf(v, v, sumsq);
        }
    }

    // ---- warp reduction for mean / unbiased std ----
    #pragma unroll
    for (int o = 16; o > 0; o >>= 1) {
        sum   += __shfl_xor_sync(0xffffffffu, sum,   o);
        sumsq += __shfl_xor_sync(0xffffffffu, sumsq, o);
    }
    const float mean = sum * (1.0f / PATCH);
    float var = (sumsq - (float)PATCH * mean * mean) * (1.0f / (PATCH - 1));
    var = fmaxf(var, 0.0f);
    const float inv = 1.0f / (sqrtf(var) + 1e-4f);

    __syncwarp();

    // ---- transposed, normalized, coalesced write ----
    float* __restrict__ ob = out + (size_t)bn * (2 * PATCH) + which * PATCH;
    #pragma unroll
    for (int t = 0; t < 10; ++t) {
        const int k = t * 32 + lane;           // output element index
        if (k < PATCH) {
            const float v = smem[warpId][k % D][k / D];  // transpose
            ob[k] = (v - mean) * inv;
        }
    }
}

extern "C" void kernel_launch(void* const* d_in, const int* in_sizes, int n_in,
                              void* d_out, int out_size)
{
    const float* img1    = (const float*)d_in[0];
    const float* img2    = (const float*)d_in[1];
    const int*   matches = (const int*)d_in[2];
    float*       out     = (float*)d_out;

    const int total_patches = BATCH * NMATCH * 2;              // 65536
    const int blocks = total_patches / WARPS_PER_BLOCK;        // 8192

    extract_patch_kernel<<<blocks, 256>>>(img1, img2, matches, out);
}